// round 12
// baseline (speedup 1.0000x reference)
#include <cuda_runtime.h>
#include <cuda_bf16.h>
#include <math.h>
#include <stdint.h>

// ---------------------------------------------------------------------------
// RotatedRetinaNet postprocess: sigmoid-max -> top-512 -> decode -> rotated IoU
// -> greedy NMS.  Output (float32): boxes(B,512,5) | scores(B,512) |
// labels(B,512) | keep(B,512)
// ---------------------------------------------------------------------------

#define K_TOP      512
#define SEL_CAP    2048
#define CAND_CAP   49152
#define PAIR_CAP   524288          // >= B * 512*511/2 : overflow impossible
#define NBINS      4096            // 12-bit radix bins (top 12 key bits)
#define MAXB       4
#define NCLS       15
#define TILE       512

typedef unsigned long long u64;
typedef unsigned int u32;
typedef unsigned short u16;

// scratch (static device globals; no allocation anywhere)
__device__ u32  g_hist[MAXB * NBINS];
__device__ u32  g_cnt[MAXB];
__device__ u64  g_cand[MAXB * CAND_CAP];
__device__ u64  g_mask[MAXB * K_TOP * 8];          // suppression bits (j>i)
__device__ float g_aux[(size_t)MAXB * K_TOP * 16]; // per-box IoU aux (4x float4)
__device__ u32  g_pair[PAIR_CAP];
__device__ u32  g_paircnt;

// ---------------------------------------------------------------------------
__global__ void k_zero(int B) {
    int i = blockIdx.x * blockDim.x + threadIdx.x;
    int nh = B * NBINS;
    if (i < nh) g_hist[i] = 0;
    if (i < B) g_cnt[i] = 0;
    if (i == 0) g_paircnt = 0;
    int nm = B * K_TOP * 8;
    if (i < nm) g_mask[i] = 0ull;
}

// coalesced cp.async-staged max/argmax over 15 classes; block-aggregated
// compaction of candidates with logit >= 0 (key >= 0x80000000, exact test).
__global__ void k_scores(const float* __restrict__ logits, int N) {
    __shared__ float sl[TILE * NCLS];        // 30720 B
    __shared__ u64  skey[TILE];
    __shared__ u32  sn, sbase0;
    int b = blockIdx.y;
    int base_anchor = blockIdx.x * TILE;
    const float* src = logits + ((size_t)b * N + base_anchor) * NCLS;
    int cnt = N - base_anchor; if (cnt > TILE) cnt = TILE;
    if (threadIdx.x == 0) sn = 0;

    bool full = (cnt == TILE);
    if (full) {
        const float4* s4 = (const float4*)src;   // 7680 floats = 1920 float4
        // group A: float4 [0,1024) -- covers anchors [0,256) (floats [0,3840))
#pragma unroll
        for (int q = 0; q < 4; q++) {
            int t = threadIdx.x + q * 256;
            u32 saddr = (u32)__cvta_generic_to_shared(&((float4*)sl)[t]);
            asm volatile("cp.async.cg.shared.global [%0], [%1], 16;\n"
                         :: "r"(saddr), "l"(s4 + t));
        }
        asm volatile("cp.async.commit_group;\n" ::: "memory");
        // group B: float4 [1024,1920)
#pragma unroll
        for (int q = 4; q < 8; q++) {
            int t = threadIdx.x + q * 256;
            if (t < 1920) {
                u32 saddr = (u32)__cvta_generic_to_shared(&((float4*)sl)[t]);
                asm volatile("cp.async.cg.shared.global [%0], [%1], 16;\n"
                             :: "r"(saddr), "l"(s4 + t));
            }
        }
        asm volatile("cp.async.commit_group;\n" ::: "memory");
        asm volatile("cp.async.wait_group 1;\n" ::: "memory");
    } else {
        int total = cnt * NCLS;
        for (int t = threadIdx.x; t < total; t += 256) sl[t] = src[t];
    }
    __syncthreads();

#pragma unroll
    for (int h = 0; h < 2; h++) {
        if (full && h == 1) {
            asm volatile("cp.async.wait_group 0;\n" ::: "memory");
            __syncthreads();
        }
        int local = threadIdx.x + h * 256;
        if (local >= cnt) break;
        const float* p = sl + local * NCLS;
        float best = p[0];
        int lab = 0;
#pragma unroll
        for (int c = 1; c < NCLS; c++) {
            float v = p[c];
            if (v > best) { best = v; lab = c; }
        }
        int i = base_anchor + local;
        u32 u = __float_as_uint(best);
        u = (u & 0x80000000u) ? ~u : (u | 0x80000000u);   // sortable-ascending
        if (u >= 0x80000000u) {                           // logit >= 0 (exact)
            u32 lo = ((~(u32)i) << 4) | (u32)lab;         // ties -> smaller idx
            atomicAdd(&g_hist[b * NBINS + (u >> 20)], 1u);
            u32 p2 = atomicAdd(&sn, 1u);
            skey[p2] = ((u64)u << 32) | (u64)lo;
        }
    }
    __syncthreads();
    u32 n = sn;
    if (n == 0) return;
    if (threadIdx.x == 0) sbase0 = atomicAdd(&g_cnt[b], n);
    __syncthreads();
    u32 bs = sbase0;
    for (u32 t = threadIdx.x; t < n; t += 256) {
        u32 pos = bs + t;
        if (pos < CAND_CAP) g_cand[b * CAND_CAP + pos] = skey[t];
    }
}

// per-image: smem suffix-scan of 4096-bin histogram -> threshold, bin-scatter,
// rank = binbase + same-bin compare, then decode + emit + IoU aux. One block.
__global__ void __launch_bounds__(1024) k_sel(const float* __restrict__ deltas,
                                              const float* __restrict__ anchors,
                                              float* __restrict__ out,
                                              int N, int B) {
    __shared__ u16 sbase[NBINS];     // suffix_excl per bin (counts fit u16)
    __shared__ u32 cursor[NBINS];    // scatter cursors
    __shared__ u64 sel[SEL_CAP];
    __shared__ u32 ssum[1024];
    __shared__ u32 sthr, stot;
    int b = blockIdx.x;
    int t = threadIdx.x;

    // 1. coalesced histogram load: thread t owns bins [4t, 4t+3]
    uint4 hv = ((const uint4*)(g_hist + b * NBINS))[t];
    u32 s = hv.x + hv.y + hv.z + hv.w;
    ssum[t] = s;
    if (t == 0) sthr = 0;
    __syncthreads();
    // 2. inclusive suffix scan over 1024 chunk sums
    for (int off = 1; off < 1024; off <<= 1) {
        u32 v = (t + off < 1024) ? ssum[t + off] : 0u;
        __syncthreads();
        ssum[t] += v;
        __syncthreads();
    }
    if (t == 0) stot = ssum[0];
    // 3. per-bin suffix_excl (keys in strictly higher bins); find threshold
    {
        u32 e3 = ssum[t] - s;        // bin 4t+3 (highest in chunk)
        u32 e2 = e3 + hv.w;
        u32 e1 = e2 + hv.z;
        u32 e0 = e1 + hv.y;
        int bn = 4 * t;
        sbase[bn + 0] = (u16)e0;  cursor[bn + 0] = e0;
        sbase[bn + 1] = (u16)e1;  cursor[bn + 1] = e1;
        sbase[bn + 2] = (u16)e2;  cursor[bn + 2] = e2;
        sbase[bn + 3] = (u16)e3;  cursor[bn + 3] = e3;
        if (e0 < K_TOP && e0 + hv.x >= K_TOP) sthr = (u32)(bn + 0);
        if (e1 < K_TOP && e1 + hv.y >= K_TOP) sthr = (u32)(bn + 1);
        if (e2 < K_TOP && e2 + hv.z >= K_TOP) sthr = (u32)(bn + 2);
        if (e3 < K_TOP && e3 + hv.w >= K_TOP) sthr = (u32)(bn + 3);
    }
    __syncthreads();
    u32 thr = sthr;
    u32 msel = (thr > 0) ? (u32)sbase[thr - 1] : stot;
    if (msel > SEL_CAP) msel = SEL_CAP;

    // 4. scatter candidates with bin >= thr into sel[] (smem atomics)
    u32 m = g_cnt[b];
    if (m > CAND_CAP) m = CAND_CAP;
    for (u32 k = t; k < m; k += 1024) {
        u64 key = g_cand[b * CAND_CAP + k];
        u32 bin = (u32)(key >> 52);
        if (bin >= thr) {
            u32 pos = atomicAdd(&cursor[bin], 1u);
            if (pos < SEL_CAP) sel[pos] = key;
        }
    }
    __syncthreads();

    // 5. rank + decode + emit
    for (u32 k = t; k < msel; k += 1024) {
        u64 key = sel[k];
        u32 bin = (u32)(key >> 52);
        u32 rbase = (u32)sbase[bin];
        u32 rend = (bin > 0) ? (u32)sbase[bin - 1] : stot;
        if (rend > msel) rend = msel;
        int rank = (int)rbase;
        for (u32 q = rbase; q < rend; q++) rank += (sel[q] > key);
        if (rank >= K_TOP) continue;

        u32 u = (u32)(key >> 32);
        u32 fb = (u & 0x80000000u) ? (u & 0x7FFFFFFFu) : ~u;
        float logit = __uint_as_float(fb);
        float score = 1.0f / (1.0f + expf(-logit));
        u32 lo = (u32)(key & 0xFFFFFFFFu);
        int idx = (int)((~(lo >> 4)) & 0x0FFFFFFFu);
        int lab = (int)(lo & 0xFu);

        const float* a = anchors + (size_t)idx * 5;
        const float* d = deltas + ((size_t)b * N + idx) * 5;
        float ax = a[0], ay = a[1], aw = a[2], ah = a[3], aa = a[4];
        float dx = d[0], dy = d[1], dw = d[2], dh = d[3], da = d[4];
        float px = ax + dx * aw;
        float py = ay + dy * ah;
        float pw = aw * expf(fminf(fmaxf(dw, -4.0f), 4.0f));
        float ph = ah * expf(fminf(fmaxf(dh, -4.0f), 4.0f));
        float pa = aa + da * 57.29577951308232f;   // 180/pi

        size_t bo = ((size_t)b * K_TOP + rank) * 5;
        out[bo + 0] = px; out[bo + 1] = py; out[bo + 2] = pw;
        out[bo + 3] = ph; out[bo + 4] = pa;
        size_t scOff = (size_t)B * K_TOP * 5;
        out[scOff + (size_t)b * K_TOP + rank] = score;
        size_t lbOff = (size_t)B * K_TOP * 6;
        out[lbOff + (size_t)b * K_TOP + rank] = (float)lab;

        // --- IoU aux: corners, aabb, circle, area ---
        float ang = pa * 0.017453292519943295f;
        float cz = cosf(ang), sn = sinf(ang);
        float hx = pw * 0.5f, hy = ph * 0.5f;
        float x0 = px + cz * (-hx) - sn * (-hy), y0 = py + sn * (-hx) + cz * (-hy);
        float x1 = px + cz * ( hx) - sn * (-hy), y1 = py + sn * ( hx) + cz * (-hy);
        float x2 = px + cz * ( hx) - sn * ( hy), y2 = py + sn * ( hx) + cz * ( hy);
        float x3 = px + cz * (-hx) - sn * ( hy), y3 = py + sn * (-hx) + cz * ( hy);
        float xmn = fminf(fminf(x0, x1), fminf(x2, x3));
        float xmx = fmaxf(fmaxf(x0, x1), fmaxf(x2, x3));
        float ymn = fminf(fminf(y0, y1), fminf(y2, y3));
        float ymx = fmaxf(fmaxf(y0, y1), fmaxf(y2, y3));
        float r = 0.5f * sqrtf(pw * pw + ph * ph);
        float4* A = (float4*)&g_aux[((size_t)b * K_TOP + rank) * 16];
        A[0] = make_float4(x0, y0, x1, y1);
        A[1] = make_float4(x2, y2, x3, y3);
        A[2] = make_float4(xmn, ymn, xmx, ymx);
        A[3] = make_float4(px, py, r, pw * ph);
    }
}

// ---------------------------------------------------------------------------
// cheap conservative rejects; balanced-triangle smem tiling: grid (32, B),
// 8 warps/block, each warp owns rows (idx, 511-idx) -> exactly 511 tests.
// Survivors buffered per-warp in smem; ONE global atomic per block, then
// coalesced copy-out.  (Same-address atomic count: ~30k -> 128.)
__global__ void k_pairs(int B) {
    __shared__ float4 sc[K_TOP];   // circle: cx, cy, r, area
    __shared__ float4 sb[K_TOP];   // aabb
    __shared__ u32 buf[8 * 511];   // per-warp survivor buffers (max 511 each)
    __shared__ u32 wcnt[8], woff[8];
    __shared__ u32 gbase;
    int b = blockIdx.y;
    for (int k = threadIdx.x; k < K_TOP; k += 256) {
        const float4* A = (const float4*)&g_aux[((size_t)b * K_TOP + k) * 16];
        sb[k] = A[2];
        sc[k] = A[3];
    }
    __syncthreads();
    int warp = threadIdx.x >> 5, lane = threadIdx.x & 31;
    int idx = blockIdx.x * 8 + warp;   // [0, 256)
    u32 run = 0;
#pragma unroll
    for (int half = 0; half < 2; half++) {
        int i = half ? (511 - idx) : idx;
        float4 a3 = sc[i];
        float4 a2 = sb[i];
        for (int j0 = i + 1; j0 < 512; j0 += 32) {
            int j = j0 + lane;
            bool ok = (j < 512);
            if (ok) {
                float4 b3 = sc[j];
                // bounding-circle reject (disjoint => inter == 0 exactly)
                float ddx = a3.x - b3.x, ddy = a3.y - b3.y;
                float rr = a3.z + b3.z + 1.0f;
                ok = (ddx * ddx + ddy * ddy <= rr * rr);
                if (ok) {
                    float4 b2 = sb[j];
                    ok = !(a2.x > b2.z + 1e-3f || b2.x > a2.z + 1e-3f ||
                           a2.y > b2.w + 1e-3f || b2.y > a2.w + 1e-3f);
                }
            }
            u32 wm = __ballot_sync(0xFFFFFFFFu, ok);
            if (ok) {
                int off = __popc(wm & ((1u << lane) - 1u));
                buf[warp * 511 + run + off] =
                    ((u32)b << 18) | ((u32)i << 9) | (u32)j;
            }
            run += (u32)__popc(wm);
        }
    }
    if (lane == 0) wcnt[warp] = run;
    __syncthreads();
    if (threadIdx.x == 0) {
        u32 tot = 0;
#pragma unroll
        for (int w = 0; w < 8; w++) { woff[w] = tot; tot += wcnt[w]; }
        gbase = atomicAdd(&g_paircnt, tot);
    }
    __syncthreads();
    u32 gb = gbase + woff[warp];
    u32 cnt = wcnt[warp];
    for (u32 k = lane; k < cnt; k += 32)
        g_pair[gb + k] = buf[warp * 511 + k];
}

// dense Sutherland-Hodgman over survivor pairs (smem scratch, grid-stride)
#define SP(slot) sp[(slot) * 128 + threadIdx.x]

__global__ void k_clip(int B) {
    __shared__ float sp[32 * 128];
    u32 total = g_paircnt;
    for (u32 idx = blockIdx.x * blockDim.x + threadIdx.x; idx < total;
         idx += gridDim.x * blockDim.x) {
        u32 pk = g_pair[idx];
        int b = (int)(pk >> 18);
        int i = (int)((pk >> 9) & 511u);
        int j = (int)(pk & 511u);
        const float4* A = (const float4*)&g_aux[((size_t)b * K_TOP + i) * 16];
        const float4* Bq = (const float4*)&g_aux[((size_t)b * K_TOP + j) * 16];
        float4 a3 = A[3], b3 = Bq[3];
        float4 a0 = A[0], a1 = A[1], b0 = Bq[0], b1 = Bq[1];
        float bx4[4] = {b0.x, b0.z, b1.x, b1.z};
        float by4[4] = {b0.y, b0.w, b1.y, b1.w};
        // subject polygon slots: cx 0..7, cy 8..15, nx 16..23, ny 24..31
        SP(0) = a0.x; SP(8)  = a0.y;
        SP(1) = a0.z; SP(9)  = a0.w;
        SP(2) = a1.x; SP(10) = a1.y;
        SP(3) = a1.z; SP(11) = a1.w;
        int n = 4;
#pragma unroll
        for (int e = 0; e < 4; e++) {
            float eax = bx4[e], eay = by4[e];
            float ebx = bx4[(e + 1) & 3], eby = by4[(e + 1) & 3];
            float ex = ebx - eax, ey = eby - eay;
            int mcnt = 0;
            for (int k = 0; k < n; k++) {
                int kn = (k + 1 == n) ? 0 : (k + 1);
                float ckx = SP(k), cky = SP(8 + k);
                float cnx = SP(kn), cny = SP(8 + kn);
                float dc = ex * (cky - eay) - ey * (ckx - eax);
                float dn = ex * (cny - eay) - ey * (cnx - eax);
                bool ci = dc >= 0.0f;
                bool ni = dn >= 0.0f;
                if (ci && mcnt < 8) { SP(16 + mcnt) = ckx; SP(24 + mcnt) = cky; mcnt++; }
                if ((ci != ni) && mcnt < 8) {
                    float den = dc - dn;
                    if (fabsf(den) < 1e-9f) den = 1e-9f;
                    float tt = dc / den;
                    SP(16 + mcnt) = ckx + tt * (cnx - ckx);
                    SP(24 + mcnt) = cky + tt * (cny - cky);
                    mcnt++;
                }
            }
            n = mcnt;
            for (int k = 0; k < n; k++) { SP(k) = SP(16 + k); SP(8 + k) = SP(24 + k); }
            if (n == 0) break;
        }
        float inter = 0.0f;
        if (n >= 3) {
            float sacc = 0.0f;
            for (int k = 0; k < n; k++) {
                int kn = (k + 1 == n) ? 0 : (k + 1);
                sacc += SP(k) * SP(8 + kn) - SP(8 + k) * SP(kn);
            }
            inter = 0.5f * fabsf(sacc);
        }
        float uni = a3.w + b3.w - inter;
        float iou = inter / fmaxf(uni, 1e-6f);
        if (iou > 0.5f)
            atomicOr(&g_mask[(size_t)b * K_TOP * 8 + (size_t)i * 8 + (j >> 6)],
                     1ull << (j & 63));
    }
}

// greedy NMS: one warp per image, bitmask in smem
__global__ void k_nms(float* __restrict__ out, int B) {
    int b = blockIdx.x;
    int lane = threadIdx.x;           // blockDim.x == 32
    __shared__ u64 sm[K_TOP * 8];
    for (int k = lane; k < K_TOP * 8; k += 32)
        sm[k] = g_mask[(size_t)b * K_TOP * 8 + k];
    __syncwarp();

    size_t scOff = (size_t)B * K_TOP * 5;
    u64 remv = 0ull;
    if (lane < 8) {
        for (int q = 0; q < 64; q++) {
            float s = out[scOff + (size_t)b * K_TOP + lane * 64 + q];
            if (!(s > 0.05f)) remv |= (1ull << q);   // invalid start removed
        }
    }
    for (int i = 0; i < K_TOP; i++) {
        int owner = i >> 6;
        u64 rw = __shfl_sync(0xFFFFFFFFu, remv, owner);
        if (!((rw >> (i & 63)) & 1ull)) {
            if (lane < 8) remv |= sm[i * 8 + lane];
        }
    }
    size_t kpOff = (size_t)B * K_TOP * 7;
    if (lane < 8) {
        for (int q = 0; q < 64; q++) {
            int j = lane * 64 + q;
            out[kpOff + (size_t)b * K_TOP + j] =
                ((remv >> q) & 1ull) ? 0.0f : 1.0f;
        }
    }
}

// ---------------------------------------------------------------------------
extern "C" void kernel_launch(void* const* d_in, const int* in_sizes, int n_in,
                              void* d_out, int out_size) {
    const float* logits = (const float*)d_in[0];
    const float* deltas = (const float*)d_in[1];
    const float* anchors = (const float*)d_in[2];
    float* out = (float*)d_out;

    int N = in_sizes[2] / 5;                 // anchors: (N,5)
    int B = in_sizes[1] / in_sizes[2];       // (B,N,5)/(N,5)
    if (B > MAXB) return;                    // scratch sized for this problem

    int zeroTot = B * K_TOP * 8;             // >= B*NBINS too
    if (B * NBINS > zeroTot) zeroTot = B * NBINS;
    k_zero<<<(zeroTot + 255) / 256, 256>>>(B);

    dim3 gs((N + TILE - 1) / TILE, B);
    k_scores<<<gs, 256>>>(logits, N);
    k_sel<<<B, 1024>>>(deltas, anchors, out, N, B);

    dim3 gp(32, B);
    k_pairs<<<gp, 256>>>(B);
    k_clip<<<1024, 128>>>(B);
    k_nms<<<B, 32>>>(out, B);
}

// round 13
// speedup vs baseline: 1.0032x; 1.0032x over previous
#include <cuda_runtime.h>
#include <cuda_bf16.h>
#include <math.h>
#include <stdint.h>

// ---------------------------------------------------------------------------
// RotatedRetinaNet postprocess: sigmoid-max -> top-512 -> decode -> rotated IoU
// -> greedy NMS.  Output (float32): boxes(B,512,5) | scores(B,512) |
// labels(B,512) | keep(B,512)
// ---------------------------------------------------------------------------

#define K_TOP      512
#define SEL_CAP    2048
#define CAND_CAP   49152
#define PAIR_CAP   524288          // >= B * 512*511/2 : overflow impossible
#define NBINS      4096            // 12-bit radix bins (top 12 key bits)
#define MAXB       4
#define NCLS       15
#define TILE       512

typedef unsigned long long u64;
typedef unsigned int u32;
typedef unsigned short u16;

// scratch (static device globals; no allocation anywhere)
__device__ u32  g_hist[MAXB * NBINS];
__device__ u32  g_cnt[MAXB];
__device__ u64  g_cand[MAXB * CAND_CAP];
__device__ u64  g_mask[MAXB * K_TOP * 8];          // suppression bits (j>i)
__device__ float g_aux[(size_t)MAXB * K_TOP * 16]; // per-box IoU aux (4x float4)
__device__ u32  g_pair[PAIR_CAP];
__device__ u32  g_paircnt;

// ---------------------------------------------------------------------------
__global__ void k_zero(int B) {
    int i = blockIdx.x * blockDim.x + threadIdx.x;
    int nh = B * NBINS;
    if (i < nh) g_hist[i] = 0;
    if (i < B) g_cnt[i] = 0;
    if (i == 0) g_paircnt = 0;
    int nm = B * K_TOP * 8;
    if (i < nm) g_mask[i] = 0ull;
}

// coalesced cp.async-staged max/argmax over 15 classes; block-aggregated
// compaction of candidates with logit >= 0 (key >= 0x80000000, exact test).
__global__ void k_scores(const float* __restrict__ logits, int N) {
    __shared__ float sl[TILE * NCLS];        // 30720 B
    __shared__ u64  skey[TILE];
    __shared__ u32  sn, sbase0;
    int b = blockIdx.y;
    int base_anchor = blockIdx.x * TILE;
    const float* src = logits + ((size_t)b * N + base_anchor) * NCLS;
    int cnt = N - base_anchor; if (cnt > TILE) cnt = TILE;
    if (threadIdx.x == 0) sn = 0;

    bool full = (cnt == TILE);
    if (full) {
        const float4* s4 = (const float4*)src;   // 7680 floats = 1920 float4
        // group A: float4 [0,1024) -- covers anchors [0,256) (floats [0,3840))
#pragma unroll
        for (int q = 0; q < 4; q++) {
            int t = threadIdx.x + q * 256;
            u32 saddr = (u32)__cvta_generic_to_shared(&((float4*)sl)[t]);
            asm volatile("cp.async.cg.shared.global [%0], [%1], 16;\n"
                         :: "r"(saddr), "l"(s4 + t));
        }
        asm volatile("cp.async.commit_group;\n" ::: "memory");
        // group B: float4 [1024,1920)
#pragma unroll
        for (int q = 4; q < 8; q++) {
            int t = threadIdx.x + q * 256;
            if (t < 1920) {
                u32 saddr = (u32)__cvta_generic_to_shared(&((float4*)sl)[t]);
                asm volatile("cp.async.cg.shared.global [%0], [%1], 16;\n"
                             :: "r"(saddr), "l"(s4 + t));
            }
        }
        asm volatile("cp.async.commit_group;\n" ::: "memory");
        asm volatile("cp.async.wait_group 1;\n" ::: "memory");
    } else {
        int total = cnt * NCLS;
        for (int t = threadIdx.x; t < total; t += 256) sl[t] = src[t];
    }
    __syncthreads();

#pragma unroll
    for (int h = 0; h < 2; h++) {
        if (full && h == 1) {
            asm volatile("cp.async.wait_group 0;\n" ::: "memory");
            __syncthreads();
        }
        int local = threadIdx.x + h * 256;
        if (local >= cnt) break;
        const float* p = sl + local * NCLS;
        float best = p[0];
        int lab = 0;
#pragma unroll
        for (int c = 1; c < NCLS; c++) {
            float v = p[c];
            if (v > best) { best = v; lab = c; }
        }
        int i = base_anchor + local;
        u32 u = __float_as_uint(best);
        u = (u & 0x80000000u) ? ~u : (u | 0x80000000u);   // sortable-ascending
        if (u >= 0x80000000u) {                           // logit >= 0 (exact)
            u32 lo = ((~(u32)i) << 4) | (u32)lab;         // ties -> smaller idx
            atomicAdd(&g_hist[b * NBINS + (u >> 20)], 1u);
            u32 p2 = atomicAdd(&sn, 1u);
            skey[p2] = ((u64)u << 32) | (u64)lo;
        }
    }
    __syncthreads();
    u32 n = sn;
    if (n == 0) return;
    if (threadIdx.x == 0) sbase0 = atomicAdd(&g_cnt[b], n);
    __syncthreads();
    u32 bs = sbase0;
    for (u32 t = threadIdx.x; t < n; t += 256) {
        u32 pos = bs + t;
        if (pos < CAND_CAP) g_cand[b * CAND_CAP + pos] = skey[t];
    }
}

// per-image: smem suffix-scan of 4096-bin histogram -> threshold, bin-scatter,
// rank = binbase + same-bin compare, then decode + emit + IoU aux. One block.
__global__ void __launch_bounds__(1024) k_sel(const float* __restrict__ deltas,
                                              const float* __restrict__ anchors,
                                              float* __restrict__ out,
                                              int N, int B) {
    __shared__ u16 sbase[NBINS];     // suffix_excl per bin (counts fit u16)
    __shared__ u32 cursor[NBINS];    // scatter cursors
    __shared__ u64 sel[SEL_CAP];
    __shared__ u32 ssum[1024];
    __shared__ u32 sthr, stot;
    int b = blockIdx.x;
    int t = threadIdx.x;

    // 1. coalesced histogram load: thread t owns bins [4t, 4t+3]
    uint4 hv = ((const uint4*)(g_hist + b * NBINS))[t];
    u32 s = hv.x + hv.y + hv.z + hv.w;
    ssum[t] = s;
    if (t == 0) sthr = 0;
    __syncthreads();
    // 2. inclusive suffix scan over 1024 chunk sums
    for (int off = 1; off < 1024; off <<= 1) {
        u32 v = (t + off < 1024) ? ssum[t + off] : 0u;
        __syncthreads();
        ssum[t] += v;
        __syncthreads();
    }
    if (t == 0) stot = ssum[0];
    // 3. per-bin suffix_excl (keys in strictly higher bins); find threshold
    {
        u32 e3 = ssum[t] - s;        // bin 4t+3 (highest in chunk)
        u32 e2 = e3 + hv.w;
        u32 e1 = e2 + hv.z;
        u32 e0 = e1 + hv.y;
        int bn = 4 * t;
        sbase[bn + 0] = (u16)e0;  cursor[bn + 0] = e0;
        sbase[bn + 1] = (u16)e1;  cursor[bn + 1] = e1;
        sbase[bn + 2] = (u16)e2;  cursor[bn + 2] = e2;
        sbase[bn + 3] = (u16)e3;  cursor[bn + 3] = e3;
        if (e0 < K_TOP && e0 + hv.x >= K_TOP) sthr = (u32)(bn + 0);
        if (e1 < K_TOP && e1 + hv.y >= K_TOP) sthr = (u32)(bn + 1);
        if (e2 < K_TOP && e2 + hv.z >= K_TOP) sthr = (u32)(bn + 2);
        if (e3 < K_TOP && e3 + hv.w >= K_TOP) sthr = (u32)(bn + 3);
    }
    __syncthreads();
    u32 thr = sthr;
    u32 msel = (thr > 0) ? (u32)sbase[thr - 1] : stot;
    if (msel > SEL_CAP) msel = SEL_CAP;

    // 4. scatter candidates with bin >= thr into sel[] (smem atomics)
    u32 m = g_cnt[b];
    if (m > CAND_CAP) m = CAND_CAP;
    for (u32 k = t; k < m; k += 1024) {
        u64 key = g_cand[b * CAND_CAP + k];
        u32 bin = (u32)(key >> 52);
        if (bin >= thr) {
            u32 pos = atomicAdd(&cursor[bin], 1u);
            if (pos < SEL_CAP) sel[pos] = key;
        }
    }
    __syncthreads();

    // 5. rank + decode + emit
    for (u32 k = t; k < msel; k += 1024) {
        u64 key = sel[k];
        u32 bin = (u32)(key >> 52);
        u32 rbase = (u32)sbase[bin];
        u32 rend = (bin > 0) ? (u32)sbase[bin - 1] : stot;
        if (rend > msel) rend = msel;
        int rank = (int)rbase;
        for (u32 q = rbase; q < rend; q++) rank += (sel[q] > key);
        if (rank >= K_TOP) continue;

        u32 u = (u32)(key >> 32);
        u32 fb = (u & 0x80000000u) ? (u & 0x7FFFFFFFu) : ~u;
        float logit = __uint_as_float(fb);
        float score = 1.0f / (1.0f + expf(-logit));
        u32 lo = (u32)(key & 0xFFFFFFFFu);
        int idx = (int)((~(lo >> 4)) & 0x0FFFFFFFu);
        int lab = (int)(lo & 0xFu);

        const float* a = anchors + (size_t)idx * 5;
        const float* d = deltas + ((size_t)b * N + idx) * 5;
        float ax = a[0], ay = a[1], aw = a[2], ah = a[3], aa = a[4];
        float dx = d[0], dy = d[1], dw = d[2], dh = d[3], da = d[4];
        float px = ax + dx * aw;
        float py = ay + dy * ah;
        float pw = aw * expf(fminf(fmaxf(dw, -4.0f), 4.0f));
        float ph = ah * expf(fminf(fmaxf(dh, -4.0f), 4.0f));
        float pa = aa + da * 57.29577951308232f;   // 180/pi

        size_t bo = ((size_t)b * K_TOP + rank) * 5;
        out[bo + 0] = px; out[bo + 1] = py; out[bo + 2] = pw;
        out[bo + 3] = ph; out[bo + 4] = pa;
        size_t scOff = (size_t)B * K_TOP * 5;
        out[scOff + (size_t)b * K_TOP + rank] = score;
        size_t lbOff = (size_t)B * K_TOP * 6;
        out[lbOff + (size_t)b * K_TOP + rank] = (float)lab;

        // --- IoU aux: corners, aabb, circle, area ---
        float ang = pa * 0.017453292519943295f;
        float cz = cosf(ang), sn = sinf(ang);
        float hx = pw * 0.5f, hy = ph * 0.5f;
        float x0 = px + cz * (-hx) - sn * (-hy), y0 = py + sn * (-hx) + cz * (-hy);
        float x1 = px + cz * ( hx) - sn * (-hy), y1 = py + sn * ( hx) + cz * (-hy);
        float x2 = px + cz * ( hx) - sn * ( hy), y2 = py + sn * ( hx) + cz * ( hy);
        float x3 = px + cz * (-hx) - sn * ( hy), y3 = py + sn * (-hx) + cz * ( hy);
        float xmn = fminf(fminf(x0, x1), fminf(x2, x3));
        float xmx = fmaxf(fmaxf(x0, x1), fmaxf(x2, x3));
        float ymn = fminf(fminf(y0, y1), fminf(y2, y3));
        float ymx = fmaxf(fmaxf(y0, y1), fmaxf(y2, y3));
        float r = 0.5f * sqrtf(pw * pw + ph * ph);
        float4* A = (float4*)&g_aux[((size_t)b * K_TOP + rank) * 16];
        A[0] = make_float4(x0, y0, x1, y1);
        A[1] = make_float4(x2, y2, x3, y3);
        A[2] = make_float4(xmn, ymn, xmx, ymx);
        A[3] = make_float4(px, py, r, pw * ph);
    }
}

// ---------------------------------------------------------------------------
// cheap conservative rejects; balanced-triangle smem tiling: grid (32, B),
// 8 warps/block, each warp owns rows (idx, 511-idx) -> exactly 511 tests.
// Survivors buffered per-warp in smem; ONE global atomic per block, then
// coalesced copy-out.  (Same-address atomic count: ~30k -> 128.)
__global__ void k_pairs(int B) {
    __shared__ float4 sc[K_TOP];   // circle: cx, cy, r, area
    __shared__ float4 sb[K_TOP];   // aabb
    __shared__ u32 buf[8 * 511];   // per-warp survivor buffers (max 511 each)
    __shared__ u32 wcnt[8], woff[8];
    __shared__ u32 gbase;
    int b = blockIdx.y;
    for (int k = threadIdx.x; k < K_TOP; k += 256) {
        const float4* A = (const float4*)&g_aux[((size_t)b * K_TOP + k) * 16];
        sb[k] = A[2];
        sc[k] = A[3];
    }
    __syncthreads();
    int warp = threadIdx.x >> 5, lane = threadIdx.x & 31;
    int idx = blockIdx.x * 8 + warp;   // [0, 256)
    u32 run = 0;
#pragma unroll
    for (int half = 0; half < 2; half++) {
        int i = half ? (511 - idx) : idx;
        float4 a3 = sc[i];
        float4 a2 = sb[i];
        for (int j0 = i + 1; j0 < 512; j0 += 32) {
            int j = j0 + lane;
            bool ok = (j < 512);
            if (ok) {
                float4 b3 = sc[j];
                // bounding-circle reject (disjoint => inter == 0 exactly)
                float ddx = a3.x - b3.x, ddy = a3.y - b3.y;
                float rr = a3.z + b3.z + 1.0f;
                ok = (ddx * ddx + ddy * ddy <= rr * rr);
                if (ok) {
                    float4 b2 = sb[j];
                    ok = !(a2.x > b2.z + 1e-3f || b2.x > a2.z + 1e-3f ||
                           a2.y > b2.w + 1e-3f || b2.y > a2.w + 1e-3f);
                }
            }
            u32 wm = __ballot_sync(0xFFFFFFFFu, ok);
            if (ok) {
                int off = __popc(wm & ((1u << lane) - 1u));
                buf[warp * 511 + run + off] =
                    ((u32)b << 18) | ((u32)i << 9) | (u32)j;
            }
            run += (u32)__popc(wm);
        }
    }
    if (lane == 0) wcnt[warp] = run;
    __syncthreads();
    if (threadIdx.x == 0) {
        u32 tot = 0;
#pragma unroll
        for (int w = 0; w < 8; w++) { woff[w] = tot; tot += wcnt[w]; }
        gbase = atomicAdd(&g_paircnt, tot);
    }
    __syncthreads();
    u32 gb = gbase + woff[warp];
    u32 cnt = wcnt[warp];
    for (u32 k = lane; k < cnt; k += 32)
        g_pair[gb + k] = buf[warp * 511 + k];
}

// dense Sutherland-Hodgman over survivor pairs (smem scratch, grid-stride)
#define SP(slot) sp[(slot) * 128 + threadIdx.x]

__global__ void k_clip(int B) {
    __shared__ float sp[32 * 128];
    u32 total = g_paircnt;
    for (u32 idx = blockIdx.x * blockDim.x + threadIdx.x; idx < total;
         idx += gridDim.x * blockDim.x) {
        u32 pk = g_pair[idx];
        int b = (int)(pk >> 18);
        int i = (int)((pk >> 9) & 511u);
        int j = (int)(pk & 511u);
        const float4* A = (const float4*)&g_aux[((size_t)b * K_TOP + i) * 16];
        const float4* Bq = (const float4*)&g_aux[((size_t)b * K_TOP + j) * 16];
        float4 a3 = A[3], b3 = Bq[3];
        float4 a0 = A[0], a1 = A[1], b0 = Bq[0], b1 = Bq[1];
        float bx4[4] = {b0.x, b0.z, b1.x, b1.z};
        float by4[4] = {b0.y, b0.w, b1.y, b1.w};
        // subject polygon slots: cx 0..7, cy 8..15, nx 16..23, ny 24..31
        SP(0) = a0.x; SP(8)  = a0.y;
        SP(1) = a0.z; SP(9)  = a0.w;
        SP(2) = a1.x; SP(10) = a1.y;
        SP(3) = a1.z; SP(11) = a1.w;
        int n = 4;
#pragma unroll
        for (int e = 0; e < 4; e++) {
            float eax = bx4[e], eay = by4[e];
            float ebx = bx4[(e + 1) & 3], eby = by4[(e + 1) & 3];
            float ex = ebx - eax, ey = eby - eay;
            int mcnt = 0;
            for (int k = 0; k < n; k++) {
                int kn = (k + 1 == n) ? 0 : (k + 1);
                float ckx = SP(k), cky = SP(8 + k);
                float cnx = SP(kn), cny = SP(8 + kn);
                float dc = ex * (cky - eay) - ey * (ckx - eax);
                float dn = ex * (cny - eay) - ey * (cnx - eax);
                bool ci = dc >= 0.0f;
                bool ni = dn >= 0.0f;
                if (ci && mcnt < 8) { SP(16 + mcnt) = ckx; SP(24 + mcnt) = cky; mcnt++; }
                if ((ci != ni) && mcnt < 8) {
                    float den = dc - dn;
                    if (fabsf(den) < 1e-9f) den = 1e-9f;
                    float tt = dc / den;
                    SP(16 + mcnt) = ckx + tt * (cnx - ckx);
                    SP(24 + mcnt) = cky + tt * (cny - cky);
                    mcnt++;
                }
            }
            n = mcnt;
            for (int k = 0; k < n; k++) { SP(k) = SP(16 + k); SP(8 + k) = SP(24 + k); }
            if (n == 0) break;
        }
        float inter = 0.0f;
        if (n >= 3) {
            float sacc = 0.0f;
            for (int k = 0; k < n; k++) {
                int kn = (k + 1 == n) ? 0 : (k + 1);
                sacc += SP(k) * SP(8 + kn) - SP(8 + k) * SP(kn);
            }
            inter = 0.5f * fabsf(sacc);
        }
        float uni = a3.w + b3.w - inter;
        float iou = inter / fmaxf(uni, 1e-6f);
        if (iou > 0.5f)
            atomicOr(&g_mask[(size_t)b * K_TOP * 8 + (size_t)i * 8 + (j >> 6)],
                     1ull << (j & 63));
    }
}

// greedy NMS: one warp per image, bitmask in smem
__global__ void k_nms(float* __restrict__ out, int B) {
    int b = blockIdx.x;
    int lane = threadIdx.x;           // blockDim.x == 32
    __shared__ u64 sm[K_TOP * 8];
    for (int k = lane; k < K_TOP * 8; k += 32)
        sm[k] = g_mask[(size_t)b * K_TOP * 8 + k];
    __syncwarp();

    size_t scOff = (size_t)B * K_TOP * 5;
    u64 remv = 0ull;
    if (lane < 8) {
        for (int q = 0; q < 64; q++) {
            float s = out[scOff + (size_t)b * K_TOP + lane * 64 + q];
            if (!(s > 0.05f)) remv |= (1ull << q);   // invalid start removed
        }
    }
    for (int i = 0; i < K_TOP; i++) {
        int owner = i >> 6;
        u64 rw = __shfl_sync(0xFFFFFFFFu, remv, owner);
        if (!((rw >> (i & 63)) & 1ull)) {
            if (lane < 8) remv |= sm[i * 8 + lane];
        }
    }
    size_t kpOff = (size_t)B * K_TOP * 7;
    if (lane < 8) {
        for (int q = 0; q < 64; q++) {
            int j = lane * 64 + q;
            out[kpOff + (size_t)b * K_TOP + j] =
                ((remv >> q) & 1ull) ? 0.0f : 1.0f;
        }
    }
}

// ---------------------------------------------------------------------------
extern "C" void kernel_launch(void* const* d_in, const int* in_sizes, int n_in,
                              void* d_out, int out_size) {
    const float* logits = (const float*)d_in[0];
    const float* deltas = (const float*)d_in[1];
    const float* anchors = (const float*)d_in[2];
    float* out = (float*)d_out;

    int N = in_sizes[2] / 5;                 // anchors: (N,5)
    int B = in_sizes[1] / in_sizes[2];       // (B,N,5)/(N,5)
    if (B > MAXB) return;                    // scratch sized for this problem

    int zeroTot = B * K_TOP * 8;             // >= B*NBINS too
    if (B * NBINS > zeroTot) zeroTot = B * NBINS;
    k_zero<<<(zeroTot + 255) / 256, 256>>>(B);

    dim3 gs((N + TILE - 1) / TILE, B);
    k_scores<<<gs, 256>>>(logits, N);
    k_sel<<<B, 1024>>>(deltas, anchors, out, N, B);

    dim3 gp(32, B);
    k_pairs<<<gp, 256>>>(B);
    k_clip<<<1024, 128>>>(B);
    k_nms<<<B, 32>>>(out, B);
}